// round 1
// baseline (speedup 1.0000x reference)
#include <cuda_runtime.h>
#include <float.h>

#define IN_DIM 256
#define OUT_DIM 512
#define MEM_LEN 131072
#define TOPK 16

__device__ float g_enc[OUT_DIM];
__device__ float g_dist[MEM_LEN];

// ---------------------------------------------------------------------------
// Kernel A: enc = tanh(xn @ W + b), xn = (data-mean)/std with std==0 -> 0
// 1 block, 512 threads (one per output column).
// ---------------------------------------------------------------------------
__global__ void enc_kernel(const float* __restrict__ data,
                           const float* __restrict__ mean,
                           const float* __restrict__ stdv,
                           const float* __restrict__ W,
                           const float* __restrict__ b) {
    __shared__ float xn[IN_DIM];
    int t = threadIdx.x;
    if (t < IN_DIM) {
        float s = stdv[t];
        xn[t] = (s == 0.0f) ? 0.0f : (data[t] - mean[t]) / s;
    }
    __syncthreads();
    float acc = b[t];
#pragma unroll 8
    for (int i = 0; i < IN_DIM; ++i) {
        acc = fmaf(xn[i], W[i * OUT_DIM + t], acc);
    }
    g_enc[t] = tanhf(acc);
}

// ---------------------------------------------------------------------------
// Kernel B: dist[row] = sum_j |memory[row][j] - enc[j]|
// One warp per row. Each lane owns 16 enc values (cols lane*4 + 128*k).
// ---------------------------------------------------------------------------
__global__ void dist_kernel(const float* __restrict__ memory) {
    int gwarp = (blockIdx.x * blockDim.x + threadIdx.x) >> 5;
    int lane  = threadIdx.x & 31;
    if (gwarp >= MEM_LEN) return;

    // enc slice in registers (broadcast-friendly, cached in L1/L2)
    float4 e0 = *(const float4*)(g_enc + 0 * 128 + lane * 4);
    float4 e1 = *(const float4*)(g_enc + 1 * 128 + lane * 4);
    float4 e2 = *(const float4*)(g_enc + 2 * 128 + lane * 4);
    float4 e3 = *(const float4*)(g_enc + 3 * 128 + lane * 4);

    const float4* m = (const float4*)(memory + (size_t)gwarp * OUT_DIM);
    float4 v0 = __ldg(&m[0 * 32 + lane]);
    float4 v1 = __ldg(&m[1 * 32 + lane]);
    float4 v2 = __ldg(&m[2 * 32 + lane]);
    float4 v3 = __ldg(&m[3 * 32 + lane]);

    float s = 0.0f;
    s += fabsf(v0.x - e0.x) + fabsf(v0.y - e0.y) + fabsf(v0.z - e0.z) + fabsf(v0.w - e0.w);
    s += fabsf(v1.x - e1.x) + fabsf(v1.y - e1.y) + fabsf(v1.z - e1.z) + fabsf(v1.w - e1.w);
    s += fabsf(v2.x - e2.x) + fabsf(v2.y - e2.y) + fabsf(v2.z - e2.z) + fabsf(v2.w - e2.w);
    s += fabsf(v3.x - e3.x) + fabsf(v3.y - e3.y) + fabsf(v3.z - e3.z) + fabsf(v3.w - e3.w);

#pragma unroll
    for (int o = 16; o > 0; o >>= 1)
        s += __shfl_xor_sync(0xFFFFFFFFu, s, o);

    if (lane == 0) g_dist[gwarp] = s;
}

// ---------------------------------------------------------------------------
// Kernel C: top-16 smallest of g_dist, loss = sum(top*exp_w)/sum(exp_w)
// 1 block, 256 threads. Per-thread insertion top-16 in shared, then tree merge.
// ---------------------------------------------------------------------------
#define TKT 256  // threads in topk kernel

__global__ void topk_kernel(const float* __restrict__ exp_w,
                            float* __restrict__ out) {
    __shared__ float sh[TKT * TOPK];
    int tid = threadIdx.x;
    float* mine = sh + tid * TOPK;

#pragma unroll
    for (int i = 0; i < TOPK; ++i) mine[i] = FLT_MAX;

    // strided scan with insertion into a sorted (ascending) list of 16
    for (int idx = tid; idx < MEM_LEN; idx += TKT) {
        float v = g_dist[idx];
        if (v < mine[TOPK - 1]) {
            int j = TOPK - 1;
            while (j > 0 && mine[j - 1] > v) {
                mine[j] = mine[j - 1];
                --j;
            }
            mine[j] = v;
        }
    }

    // tree merge of sorted 16-lists: keep 16 smallest of each pair
    for (int s = TKT / 2; s >= 1; s >>= 1) {
        __syncthreads();
        if (tid < s) {
            float* a = sh + tid * TOPK;
            float* c = sh + (tid + s) * TOPK;
            float merged[TOPK];
            int ia = 0, ib = 0;
#pragma unroll
            for (int i = 0; i < TOPK; ++i) {
                float av = a[ia];
                float bv = c[ib];
                if (av <= bv) { merged[i] = av; ++ia; }
                else          { merged[i] = bv; ++ib; }
            }
#pragma unroll
            for (int i = 0; i < TOPK; ++i) a[i] = merged[i];
        }
    }
    __syncthreads();

    if (tid == 0) {
        float num = 0.0f, den = 0.0f;
#pragma unroll
        for (int i = 0; i < TOPK; ++i) {
            float w = exp_w[i];
            num = fmaf(sh[i], w, num);
            den += w;
        }
        out[0] = num / den;
    }
}

// ---------------------------------------------------------------------------
// Launch
// Inputs (metadata order): data[256], mean[256], std[256],
//   memory[131072*512], W[256*512], b[512], exp_w[16]
// Output: 1 float
// ---------------------------------------------------------------------------
extern "C" void kernel_launch(void* const* d_in, const int* in_sizes, int n_in,
                              void* d_out, int out_size) {
    const float* data   = (const float*)d_in[0];
    const float* mean   = (const float*)d_in[1];
    const float* stdv   = (const float*)d_in[2];
    const float* memory = (const float*)d_in[3];
    const float* W      = (const float*)d_in[4];
    const float* b      = (const float*)d_in[5];
    const float* exp_w  = (const float*)d_in[6];
    float* out = (float*)d_out;

    enc_kernel<<<1, OUT_DIM>>>(data, mean, stdv, W, b);

    // one warp per row: 131072 rows / (256/32 warps per block) = 16384 blocks
    dist_kernel<<<MEM_LEN / 8, 256>>>(memory);

    topk_kernel<<<1, TKT>>>(exp_w, out);
}

// round 2
// speedup vs baseline: 4.2147x; 4.2147x over previous
#include <cuda_runtime.h>
#include <float.h>

#define IN_DIM 256
#define OUT_DIM 512
#define MEM_LEN 131072
#define TOPK 16

#define ENC_PARTS 32           // K-split blocks for the GEMV
#define ROWS_PER_PART (IN_DIM / ENC_PARTS)   // 8

#define TK1_BLOCKS 128
#define TK1_N (MEM_LEN / TK1_BLOCKS)         // 1024 elems per stage-1 block
#define TK1_NT 256
#define CAND_N (TK1_BLOCKS * TOPK)           // 2048 stage-2 inputs
#define TK2_NT 256

__device__ float g_enc[OUT_DIM];
__device__ float g_dist[MEM_LEN];
__device__ float g_part[ENC_PARTS * OUT_DIM];
__device__ float g_cand[CAND_N];

// ---------------------------------------------------------------------------
// Kernel A1: partial GEMV. Block p covers input rows [p*8, p*8+8).
// 32 blocks x 512 threads, coalesced W reads, parallel over the whole chip.
// ---------------------------------------------------------------------------
__global__ void enc_partial_kernel(const float* __restrict__ data,
                                   const float* __restrict__ mean,
                                   const float* __restrict__ stdv,
                                   const float* __restrict__ W) {
    __shared__ float xn[ROWS_PER_PART];
    int t = threadIdx.x;              // 0..511 = output column
    int r0 = blockIdx.x * ROWS_PER_PART;
    if (t < ROWS_PER_PART) {
        int r = r0 + t;
        float s = stdv[r];
        xn[t] = (s == 0.0f) ? 0.0f : (data[r] - mean[r]) / s;
    }
    __syncthreads();
    float acc = 0.0f;
#pragma unroll
    for (int i = 0; i < ROWS_PER_PART; ++i)
        acc = fmaf(xn[i], W[(size_t)(r0 + i) * OUT_DIM + t], acc);
    g_part[blockIdx.x * OUT_DIM + t] = acc;
}

// ---------------------------------------------------------------------------
// Kernel A2: reduce partials, add bias, tanh. 1 block x 512 (L2-hit reads).
// ---------------------------------------------------------------------------
__global__ void enc_finish_kernel(const float* __restrict__ b) {
    int t = threadIdx.x;
    float acc = b[t];
#pragma unroll
    for (int p = 0; p < ENC_PARTS; ++p)
        acc += g_part[p * OUT_DIM + t];
    g_enc[t] = tanhf(acc);
}

// ---------------------------------------------------------------------------
// Kernel B: dist[row] = sum |memory[row] - enc|. One warp per row,
// 512 thr/block (16 rows/block), enc staged in shared.
// ---------------------------------------------------------------------------
__global__ void dist_kernel(const float* __restrict__ memory) {
    __shared__ float se[OUT_DIM];
    int t = threadIdx.x;
    se[t] = g_enc[t];
    __syncthreads();

    int warp = t >> 5;
    int lane = t & 31;
    int row  = blockIdx.x * 16 + warp;

    const float4* es = (const float4*)se;
    float4 e0 = es[0 * 32 + lane];
    float4 e1 = es[1 * 32 + lane];
    float4 e2 = es[2 * 32 + lane];
    float4 e3 = es[3 * 32 + lane];

    const float4* m = (const float4*)(memory + (size_t)row * OUT_DIM);
    float4 v0 = __ldg(&m[0 * 32 + lane]);
    float4 v1 = __ldg(&m[1 * 32 + lane]);
    float4 v2 = __ldg(&m[2 * 32 + lane]);
    float4 v3 = __ldg(&m[3 * 32 + lane]);

    float s = 0.0f;
    s += fabsf(v0.x - e0.x) + fabsf(v0.y - e0.y) + fabsf(v0.z - e0.z) + fabsf(v0.w - e0.w);
    s += fabsf(v1.x - e1.x) + fabsf(v1.y - e1.y) + fabsf(v1.z - e1.z) + fabsf(v1.w - e1.w);
    s += fabsf(v2.x - e2.x) + fabsf(v2.y - e2.y) + fabsf(v2.z - e2.z) + fabsf(v2.w - e2.w);
    s += fabsf(v3.x - e3.x) + fabsf(v3.y - e3.y) + fabsf(v3.z - e3.z) + fabsf(v3.w - e3.w);

#pragma unroll
    for (int o = 16; o > 0; o >>= 1)
        s += __shfl_xor_sync(0xFFFFFFFFu, s, o);

    if (lane == 0) g_dist[row] = s;
}

// ---------------------------------------------------------------------------
// Kernel C1: per-block top-16 via shared bitonic sort of 1024 elems.
// 128 blocks x 256 threads; g_dist is L2-resident (512 KB).
// ---------------------------------------------------------------------------
__global__ void topk_stage1_kernel() {
    __shared__ float buf[TK1_N];
    int tid = threadIdx.x;
    int base = blockIdx.x * TK1_N;
    for (int i = tid; i < TK1_N; i += TK1_NT)
        buf[i] = g_dist[base + i];

    for (int k = 2; k <= TK1_N; k <<= 1) {
        for (int j = k >> 1; j > 0; j >>= 1) {
            __syncthreads();
            for (int i = tid; i < TK1_N; i += TK1_NT) {
                int ixj = i ^ j;
                if (ixj > i) {
                    float a = buf[i], c = buf[ixj];
                    bool up = ((i & k) == 0);
                    if ((a > c) == up) { buf[i] = c; buf[ixj] = a; }
                }
            }
        }
    }
    __syncthreads();
    if (tid < TOPK)
        g_cand[blockIdx.x * TOPK + tid] = buf[tid];
}

// ---------------------------------------------------------------------------
// Kernel C2: sort 2048 candidates, take 16 smallest, weighted loss.
// ---------------------------------------------------------------------------
__global__ void topk_stage2_kernel(const float* __restrict__ exp_w,
                                   float* __restrict__ out) {
    __shared__ float buf[CAND_N];
    int tid = threadIdx.x;
    for (int i = tid; i < CAND_N; i += TK2_NT)
        buf[i] = g_cand[i];

    for (int k = 2; k <= CAND_N; k <<= 1) {
        for (int j = k >> 1; j > 0; j >>= 1) {
            __syncthreads();
            for (int i = tid; i < CAND_N; i += TK2_NT) {
                int ixj = i ^ j;
                if (ixj > i) {
                    float a = buf[i], c = buf[ixj];
                    bool up = ((i & k) == 0);
                    if ((a > c) == up) { buf[i] = c; buf[ixj] = a; }
                }
            }
        }
    }
    __syncthreads();

    if (tid == 0) {
        float num = 0.0f, den = 0.0f;
#pragma unroll
        for (int i = 0; i < TOPK; ++i) {
            float w = exp_w[i];
            num = fmaf(buf[i], w, num);
            den += w;
        }
        out[0] = num / den;
    }
}

// ---------------------------------------------------------------------------
// Launch.
// Inputs: data[256], mean[256], std[256], memory[131072*512],
//         W[256*512], b[512], exp_w[16]  ->  out[1] float
// ---------------------------------------------------------------------------
extern "C" void kernel_launch(void* const* d_in, const int* in_sizes, int n_in,
                              void* d_out, int out_size) {
    const float* data   = (const float*)d_in[0];
    const float* mean   = (const float*)d_in[1];
    const float* stdv   = (const float*)d_in[2];
    const float* memory = (const float*)d_in[3];
    const float* W      = (const float*)d_in[4];
    const float* b      = (const float*)d_in[5];
    const float* exp_w  = (const float*)d_in[6];
    float* out = (float*)d_out;

    enc_partial_kernel<<<ENC_PARTS, OUT_DIM>>>(data, mean, stdv, W);
    enc_finish_kernel<<<1, OUT_DIM>>>(b);
    dist_kernel<<<MEM_LEN / 16, 512>>>(memory);
    topk_stage1_kernel<<<TK1_BLOCKS, TK1_NT>>>();
    topk_stage2_kernel<<<1, TK2_NT>>>(exp_w, out);
}